// round 3
// baseline (speedup 1.0000x reference)
#include <cuda_runtime.h>
#include <math.h>

#define NN 8192
#define DD 128
#define NC 256
#define SPLITS 8
#define CPS (NN / SPLITS)   // 1024 columns per split
#define TILE 128

// Scratch (device globals — no allocation allowed)
__device__ float g_xn[NN * DD];
__device__ float g_sq[NN];
__device__ int   g_lab[NN];
__device__ int   g_cnt[NC];
__device__ int   g_is64;
__device__ float g_posV[SPLITS * NN];
__device__ int   g_posI[SPLITS * NN];
__device__ float g_negV[SPLITS * NN];
__device__ int   g_negI[SPLITS * NN];

#define F_INF  __int_as_float(0x7f800000)

// Detect whether labels are stored as int64 (labels < 256, so if int64 every
// high 32-bit word is zero; if int32 the odd words are labels, ~certainly nonzero)
__global__ void detect_kernel(const int* __restrict__ labw) {
    if (threadIdx.x == 0) {
        int any = 0;
        for (int i = 0; i < 256; i++) any |= labw[2 * i + 1];
        g_is64 = (any == 0) ? 1 : 0;
    }
}

__global__ void convert_labels_kernel(const void* __restrict__ labels) {
    int i = blockIdx.x * blockDim.x + threadIdx.x;
    if (i >= NN) return;
    int v;
    if (g_is64) v = (int)((const long long*)labels)[i];
    else        v = ((const int*)labels)[i];
    g_lab[i] = v;
    if (i < NC) g_cnt[i] = 0;
}

__global__ void hist_kernel() {
    int i = blockIdx.x * blockDim.x + threadIdx.x;
    if (i < NN) atomicAdd(&g_cnt[g_lab[i] & (NC - 1)], 1);
}

// One block (128 threads) per row: normalize, then recompute sq of normalized row
__global__ void normalize_kernel(const float* __restrict__ x) {
    int row = blockIdx.x;
    int t = threadIdx.x;
    float v = x[row * DD + t];
    float s = v * v;
    #pragma unroll
    for (int o = 16; o > 0; o >>= 1) s += __shfl_xor_sync(0xffffffffu, s, o);
    __shared__ float ws[4];
    __shared__ float ws2[4];
    int warp = t >> 5, lane = t & 31;
    if (lane == 0) ws[warp] = s;
    __syncthreads();
    float tot = ws[0] + ws[1] + ws[2] + ws[3];
    float nrm = __fsqrt_rn(tot);          // IEEE, matches jnp
    float xn  = __fdiv_rn(v, nrm);        // IEEE divide, matches x / norm
    g_xn[row * DD + t] = xn;
    float s2 = xn * xn;
    #pragma unroll
    for (int o = 16; o > 0; o >>= 1) s2 += __shfl_xor_sync(0xffffffffu, s2, o);
    if (lane == 0) ws2[warp] = s2;
    __syncthreads();
    if (t == 0) g_sq[row] = ws2[0] + ws2[1] + ws2[2] + ws2[3];
}

// SGEMM-style miner: CTA = 128 anchor rows x one 1024-column split.
// 256 threads, 8x8 register micro-tile, k-chunks of 8 in shared.
__global__ void __launch_bounds__(256, 2)
mine_kernel() {
    const int rowBase  = blockIdx.x * TILE;
    const int colStart = blockIdx.y * CPS;

    __shared__ float As[8][TILE];
    __shared__ float Bs[8][TILE];
    __shared__ float sSqRow[TILE];
    __shared__ float sSqCol[TILE];
    __shared__ int   sLabRow[TILE];
    __shared__ int   sLabCol[TILE];
    __shared__ float sPV[TILE][16];
    __shared__ int   sPI[TILE][16];
    __shared__ float sNV[TILE][16];
    __shared__ int   sNI[TILE][16];

    const int tid = threadIdx.x;
    const int tx = tid & 15;      // column group 0..15
    const int ty = tid >> 4;      // row group 0..15

    for (int t = tid; t < TILE; t += 256) {
        sLabRow[t] = g_lab[rowBase + t];
        sSqRow[t]  = g_sq[rowBase + t];
    }

    float posV[8], negV[8];
    int   posI[8], negI[8];
    #pragma unroll
    for (int ii = 0; ii < 8; ii++) {
        posV[ii] = -1.0f;  posI[ii] = 0x7fffffff;
        negV[ii] = F_INF;  negI[ii] = 0x7fffffff;
    }

    const int loadRow = tid >> 1;          // 0..127
    const int loadK4  = (tid & 1) * 4;     // 0 or 4

    for (int tile = 0; tile < CPS / TILE; ++tile) {
        const int colBase = colStart + tile * TILE;
        __syncthreads();   // previous epilogue done with sLabCol/sSqCol
        for (int t = tid; t < TILE; t += 256) {
            sLabCol[t] = g_lab[colBase + t];
            sSqCol[t]  = g_sq[colBase + t];
        }

        float acc[8][8];
        #pragma unroll
        for (int i = 0; i < 8; i++)
            #pragma unroll
            for (int j = 0; j < 8; j++) acc[i][j] = 0.0f;

        for (int kk = 0; kk < DD; kk += 8) {
            __syncthreads();
            {
                float4 av = *(const float4*)&g_xn[(rowBase + loadRow) * DD + kk + loadK4];
                As[loadK4 + 0][loadRow] = av.x;
                As[loadK4 + 1][loadRow] = av.y;
                As[loadK4 + 2][loadRow] = av.z;
                As[loadK4 + 3][loadRow] = av.w;
                float4 bv = *(const float4*)&g_xn[(colBase + loadRow) * DD + kk + loadK4];
                Bs[loadK4 + 0][loadRow] = bv.x;
                Bs[loadK4 + 1][loadRow] = bv.y;
                Bs[loadK4 + 2][loadRow] = bv.z;
                Bs[loadK4 + 3][loadRow] = bv.w;
            }
            __syncthreads();
            #pragma unroll
            for (int k = 0; k < 8; k++) {
                float4 a0 = *(const float4*)&As[k][ty * 8];
                float4 a1 = *(const float4*)&As[k][ty * 8 + 4];
                float4 b0 = *(const float4*)&Bs[k][tx * 8];
                float4 b1 = *(const float4*)&Bs[k][tx * 8 + 4];
                float a[8] = {a0.x, a0.y, a0.z, a0.w, a1.x, a1.y, a1.z, a1.w};
                float b[8] = {b0.x, b0.y, b0.z, b0.w, b1.x, b1.y, b1.z, b1.w};
                #pragma unroll
                for (int i = 0; i < 8; i++)
                    #pragma unroll
                    for (int j = 0; j < 8; j++)
                        acc[i][j] = fmaf(a[i], b[j], acc[i][j]);
            }
        }

        // Epilogue: dist = sqrt(max(sq_i + sq_j - 2*dot, 0)) — IEEE sqrt to
        // reproduce the reference values. Positives masked to 0.0, negatives
        // masked to +inf; strict compares keep the first (smallest) index.
        #pragma unroll
        for (int ii = 0; ii < 8; ii++) {
            const int  i   = rowBase + ty * 8 + ii;
            const int  lr  = sLabRow[ty * 8 + ii];
            const float sr = sSqRow[ty * 8 + ii];
            #pragma unroll
            for (int jj = 0; jj < 8; jj++) {
                const int jc = tx * 8 + jj;
                const int j  = colBase + jc;
                float d2 = fmaxf(sr + sSqCol[jc] - 2.0f * acc[ii][jj], 0.0f);
                float dist = __fsqrt_rn(d2);
                const bool same = (lr == sLabCol[jc]);
                const float pv = (same && (i != j)) ? dist : 0.0f;
                if (pv > posV[ii]) { posV[ii] = pv; posI[ii] = j; }
                const float nv = same ? F_INF : dist;
                if (nv < negV[ii]) { negV[ii] = nv; negI[ii] = j; }
            }
        }
    }

    // Cross-thread reduction over the 16 tx groups per row
    __syncthreads();
    #pragma unroll
    for (int ii = 0; ii < 8; ii++) {
        const int lrow = ty * 8 + ii;
        sPV[lrow][tx] = posV[ii];  sPI[lrow][tx] = posI[ii];
        sNV[lrow][tx] = negV[ii];  sNI[lrow][tx] = negI[ii];
    }
    __syncthreads();
    if (tid < TILE) {
        float bpv = -1.0f;  int bpi = 0x7fffffff;
        float bnv = F_INF;  int bni = 0x7fffffff;
        #pragma unroll
        for (int t = 0; t < 16; t++) {
            float v = sPV[tid][t]; int id = sPI[tid][t];
            if (v > bpv || (v == bpv && id < bpi)) { bpv = v; bpi = id; }
            v = sNV[tid][t]; id = sNI[tid][t];
            if (v < bnv || (v == bnv && id < bni)) { bnv = v; bni = id; }
        }
        const int gi = rowBase + tid;
        g_posV[blockIdx.y * NN + gi] = bpv;
        g_posI[blockIdx.y * NN + gi] = bpi;
        g_negV[blockIdx.y * NN + gi] = bnv;
        g_negI[blockIdx.y * NN + gi] = bni;
    }
}

// Outputs are written as FLOAT32: the harness normalizes the reference's
// mixed int/bool tuple to float32 for the rel-err check (indices < 8192 are
// exactly representable).
__global__ void final_kernel(float* __restrict__ out) {
    int i = blockIdx.x * blockDim.x + threadIdx.x;
    if (i >= NN) return;
    float bpv = -1.0f;  int bpi = 0x7fffffff;
    float bnv = F_INF;  int bni = 0x7fffffff;
    #pragma unroll
    for (int s = 0; s < SPLITS; s++) {
        float v = g_posV[s * NN + i]; int id = g_posI[s * NN + i];
        if (v > bpv || (v == bpv && id < bpi)) { bpv = v; bpi = id; }
        v = g_negV[s * NN + i]; id = g_negI[s * NN + i];
        if (v < bnv || (v == bnv && id < bni)) { bnv = v; bni = id; }
    }
    const int c = g_cnt[g_lab[i] & (NC - 1)];
    const float keep = (c >= 2 && c < NN) ? 1.0f : 0.0f;
    out[0 * NN + i] = (float)i;    // anchor_inds
    out[1 * NN + i] = (float)bpi;  // hardest_pos_inds
    out[2 * NN + i] = (float)bni;  // hardest_neg_inds
    out[3 * NN + i] = keep;        // keep
}

extern "C" void kernel_launch(void* const* d_in, const int* in_sizes, int n_in,
                              void* d_out, int out_size) {
    const float* embeds = (const float*)d_in[0];
    const void*  labels = d_in[1];
    float* out = (float*)d_out;

    detect_kernel<<<1, 32>>>((const int*)labels);
    convert_labels_kernel<<<(NN + 255) / 256, 256>>>(labels);
    hist_kernel<<<(NN + 255) / 256, 256>>>();
    normalize_kernel<<<NN, DD>>>(embeds);
    dim3 grid(NN / TILE, SPLITS);
    mine_kernel<<<grid, 256>>>();
    final_kernel<<<(NN + 255) / 256, 256>>>(out);
}

// round 4
// speedup vs baseline: 1.0476x; 1.0476x over previous
#include <cuda_runtime.h>
#include <math.h>

#define NN 8192
#define DD 128
#define NC 256
#define SPLITS 8
#define CPS (NN / SPLITS)   // 1024 columns per split
#define TILE 128

typedef unsigned long long u64t;

// Scratch (device globals — no allocation allowed)
__device__ float g_xn[NN * DD];
__device__ float g_sq[NN];
__device__ int   g_lab[NN];
__device__ int   g_cnt[NC];
__device__ int   g_is64;
__device__ float g_posV[SPLITS * NN];
__device__ int   g_posI[SPLITS * NN];
__device__ float g_negV[SPLITS * NN];
__device__ int   g_negI[SPLITS * NN];

#define F_INF  __int_as_float(0x7f800000)

// Packed fp32x2 helpers (each lane is IEEE fp32 fma.rn — bitwise identical
// to scalar fmaf; ptxas will not generate FFMA2 from C++, PTX-only path)
__device__ __forceinline__ u64t pack2_dup(float v) {
    u64t r; asm("mov.b64 %0, {%1, %1};" : "=l"(r) : "f"(v)); return r;
}
__device__ __forceinline__ void ffma2(u64t& d, u64t a, u64t b) {
    asm("fma.rn.f32x2 %0, %1, %2, %0;" : "+l"(d) : "l"(a), "l"(b));
}
__device__ __forceinline__ void unpack2(float& lo, float& hi, u64t v) {
    asm("mov.b64 {%0, %1}, %2;" : "=f"(lo), "=f"(hi) : "l"(v));
}

// Detect whether labels are stored as int64 (labels < 256, so if int64 every
// high 32-bit word is zero; if int32 the odd words are labels, ~certainly nonzero)
__global__ void detect_kernel(const int* __restrict__ labw) {
    if (threadIdx.x == 0) {
        int any = 0;
        for (int i = 0; i < 256; i++) any |= labw[2 * i + 1];
        g_is64 = (any == 0) ? 1 : 0;
    }
}

__global__ void convert_labels_kernel(const void* __restrict__ labels) {
    int i = blockIdx.x * blockDim.x + threadIdx.x;
    if (i >= NN) return;
    int v;
    if (g_is64) v = (int)((const long long*)labels)[i];
    else        v = ((const int*)labels)[i];
    g_lab[i] = v;
    if (i < NC) g_cnt[i] = 0;
}

__global__ void hist_kernel() {
    int i = blockIdx.x * blockDim.x + threadIdx.x;
    if (i < NN) atomicAdd(&g_cnt[g_lab[i] & (NC - 1)], 1);
}

// One block (128 threads) per row: normalize, then recompute sq of normalized row
__global__ void normalize_kernel(const float* __restrict__ x) {
    int row = blockIdx.x;
    int t = threadIdx.x;
    float v = x[row * DD + t];
    float s = v * v;
    #pragma unroll
    for (int o = 16; o > 0; o >>= 1) s += __shfl_xor_sync(0xffffffffu, s, o);
    __shared__ float ws[4];
    __shared__ float ws2[4];
    int warp = t >> 5, lane = t & 31;
    if (lane == 0) ws[warp] = s;
    __syncthreads();
    float tot = ws[0] + ws[1] + ws[2] + ws[3];
    float nrm = __fsqrt_rn(tot);          // IEEE, matches jnp
    float xn  = __fdiv_rn(v, nrm);        // IEEE divide, matches x / norm
    g_xn[row * DD + t] = xn;
    float s2 = xn * xn;
    #pragma unroll
    for (int o = 16; o > 0; o >>= 1) s2 += __shfl_xor_sync(0xffffffffu, s2, o);
    if (lane == 0) ws2[warp] = s2;
    __syncthreads();
    if (t == 0) g_sq[row] = ws2[0] + ws2[1] + ws2[2] + ws2[3];
}

// SGEMM-style miner: CTA = 128 anchor rows x one 1024-column split.
// 256 threads, 8x8 register micro-tile computed as 8 rows x 4 packed
// f32x2 column-pairs (FFMA2 = 2x fp32 throughput on the fma pipe).
__global__ void __launch_bounds__(256, 2)
mine_kernel() {
    const int rowBase  = blockIdx.x * TILE;
    const int colStart = blockIdx.y * CPS;

    __shared__ float As[8][TILE];
    __shared__ float Bs[8][TILE];
    __shared__ float sSqRow[TILE];
    __shared__ float sSqCol[TILE];
    __shared__ int   sLabRow[TILE];
    __shared__ int   sLabCol[TILE];
    __shared__ float sPV[TILE][16];
    __shared__ int   sPI[TILE][16];
    __shared__ float sNV[TILE][16];
    __shared__ int   sNI[TILE][16];

    const int tid = threadIdx.x;
    const int tx = tid & 15;      // column group 0..15
    const int ty = tid >> 4;      // row group 0..15

    for (int t = tid; t < TILE; t += 256) {
        sLabRow[t] = g_lab[rowBase + t];
        sSqRow[t]  = g_sq[rowBase + t];
    }

    float posV[8], negV[8];
    int   posI[8], negI[8];
    #pragma unroll
    for (int ii = 0; ii < 8; ii++) {
        posV[ii] = -1.0f;  posI[ii] = 0x7fffffff;
        negV[ii] = F_INF;  negI[ii] = 0x7fffffff;
    }

    const int loadRow = tid >> 1;          // 0..127
    const int loadK4  = (tid & 1) * 4;     // 0 or 4

    for (int tile = 0; tile < CPS / TILE; ++tile) {
        const int colBase = colStart + tile * TILE;
        __syncthreads();   // previous epilogue done with sLabCol/sSqCol
        for (int t = tid; t < TILE; t += 256) {
            sLabCol[t] = g_lab[colBase + t];
            sSqCol[t]  = g_sq[colBase + t];
        }

        // 8 rows x 4 column-pairs of packed f32x2 accumulators (zero-init)
        u64t acc2[8][4];
        #pragma unroll
        for (int i = 0; i < 8; i++)
            #pragma unroll
            for (int p = 0; p < 4; p++) acc2[i][p] = 0ull;

        for (int kk = 0; kk < DD; kk += 8) {
            __syncthreads();
            {
                float4 av = *(const float4*)&g_xn[(rowBase + loadRow) * DD + kk + loadK4];
                As[loadK4 + 0][loadRow] = av.x;
                As[loadK4 + 1][loadRow] = av.y;
                As[loadK4 + 2][loadRow] = av.z;
                As[loadK4 + 3][loadRow] = av.w;
                float4 bv = *(const float4*)&g_xn[(colBase + loadRow) * DD + kk + loadK4];
                Bs[loadK4 + 0][loadRow] = bv.x;
                Bs[loadK4 + 1][loadRow] = bv.y;
                Bs[loadK4 + 2][loadRow] = bv.z;
                Bs[loadK4 + 3][loadRow] = bv.w;
            }
            __syncthreads();
            #pragma unroll
            for (int k = 0; k < 8; k++) {
                float4 a0 = *(const float4*)&As[k][ty * 8];
                float4 a1 = *(const float4*)&As[k][ty * 8 + 4];
                // B column-pairs: contiguous in shared, reinterpret LDS.128
                ulonglong2 bq0 = *(const ulonglong2*)&Bs[k][tx * 8];
                ulonglong2 bq1 = *(const ulonglong2*)&Bs[k][tx * 8 + 4];
                u64t bp[4] = {bq0.x, bq0.y, bq1.x, bq1.y};
                u64t a2[8];
                a2[0] = pack2_dup(a0.x); a2[1] = pack2_dup(a0.y);
                a2[2] = pack2_dup(a0.z); a2[3] = pack2_dup(a0.w);
                a2[4] = pack2_dup(a1.x); a2[5] = pack2_dup(a1.y);
                a2[6] = pack2_dup(a1.z); a2[7] = pack2_dup(a1.w);
                #pragma unroll
                for (int i = 0; i < 8; i++)
                    #pragma unroll
                    for (int p = 0; p < 4; p++)
                        ffma2(acc2[i][p], a2[i], bp[p]);
            }
        }

        // Epilogue: dist = sqrt(max(sq_i + sq_j - 2*dot, 0)) — IEEE sqrt to
        // reproduce the reference values. Positives masked to 0.0, negatives
        // masked to +inf; strict compares keep the first (smallest) index.
        #pragma unroll
        for (int ii = 0; ii < 8; ii++) {
            const int  i   = rowBase + ty * 8 + ii;
            const int  lr  = sLabRow[ty * 8 + ii];
            const float sr = sSqRow[ty * 8 + ii];
            #pragma unroll
            for (int p = 0; p < 4; p++) {
                float d_lo, d_hi;
                unpack2(d_lo, d_hi, acc2[ii][p]);
                const float dotv[2] = {d_lo, d_hi};
                #pragma unroll
                for (int q = 0; q < 2; q++) {
                    const int jc = tx * 8 + p * 2 + q;
                    const int j  = colBase + jc;
                    float d2 = fmaxf(sr + sSqCol[jc] - 2.0f * dotv[q], 0.0f);
                    float dist = __fsqrt_rn(d2);
                    const bool same = (lr == sLabCol[jc]);
                    const float pv = (same && (i != j)) ? dist : 0.0f;
                    if (pv > posV[ii]) { posV[ii] = pv; posI[ii] = j; }
                    const float nv = same ? F_INF : dist;
                    if (nv < negV[ii]) { negV[ii] = nv; negI[ii] = j; }
                }
            }
        }
    }

    // Cross-thread reduction over the 16 tx groups per row
    __syncthreads();
    #pragma unroll
    for (int ii = 0; ii < 8; ii++) {
        const int lrow = ty * 8 + ii;
        sPV[lrow][tx] = posV[ii];  sPI[lrow][tx] = posI[ii];
        sNV[lrow][tx] = negV[ii];  sNI[lrow][tx] = negI[ii];
    }
    __syncthreads();
    if (tid < TILE) {
        float bpv = -1.0f;  int bpi = 0x7fffffff;
        float bnv = F_INF;  int bni = 0x7fffffff;
        #pragma unroll
        for (int t = 0; t < 16; t++) {
            float v = sPV[tid][t]; int id = sPI[tid][t];
            if (v > bpv || (v == bpv && id < bpi)) { bpv = v; bpi = id; }
            v = sNV[tid][t]; id = sNI[tid][t];
            if (v < bnv || (v == bnv && id < bni)) { bnv = v; bni = id; }
        }
        const int gi = rowBase + tid;
        g_posV[blockIdx.y * NN + gi] = bpv;
        g_posI[blockIdx.y * NN + gi] = bpi;
        g_negV[blockIdx.y * NN + gi] = bnv;
        g_negI[blockIdx.y * NN + gi] = bni;
    }
}

// Outputs written as FLOAT32 (harness normalizes reference int/bool outputs
// to float32; indices < 8192 are exactly representable).
__global__ void final_kernel(float* __restrict__ out) {
    int i = blockIdx.x * blockDim.x + threadIdx.x;
    if (i >= NN) return;
    float bpv = -1.0f;  int bpi = 0x7fffffff;
    float bnv = F_INF;  int bni = 0x7fffffff;
    #pragma unroll
    for (int s = 0; s < SPLITS; s++) {
        float v = g_posV[s * NN + i]; int id = g_posI[s * NN + i];
        if (v > bpv || (v == bpv && id < bpi)) { bpv = v; bpi = id; }
        v = g_negV[s * NN + i]; id = g_negI[s * NN + i];
        if (v < bnv || (v == bnv && id < bni)) { bnv = v; bni = id; }
    }
    const int c = g_cnt[g_lab[i] & (NC - 1)];
    const float keep = (c >= 2 && c < NN) ? 1.0f : 0.0f;
    out[0 * NN + i] = (float)i;    // anchor_inds
    out[1 * NN + i] = (float)bpi;  // hardest_pos_inds
    out[2 * NN + i] = (float)bni;  // hardest_neg_inds
    out[3 * NN + i] = keep;        // keep
}

extern "C" void kernel_launch(void* const* d_in, const int* in_sizes, int n_in,
                              void* d_out, int out_size) {
    const float* embeds = (const float*)d_in[0];
    const void*  labels = d_in[1];
    float* out = (float*)d_out;

    detect_kernel<<<1, 32>>>((const int*)labels);
    convert_labels_kernel<<<(NN + 255) / 256, 256>>>(labels);
    hist_kernel<<<(NN + 255) / 256, 256>>>();
    normalize_kernel<<<NN, DD>>>(embeds);
    dim3 grid(NN / TILE, SPLITS);
    mine_kernel<<<grid, 256>>>();
    final_kernel<<<(NN + 255) / 256, 256>>>(out);
}

// round 5
// speedup vs baseline: 1.1424x; 1.0905x over previous
#include <cuda_runtime.h>
#include <math.h>

#define NN 8192
#define DD 128
#define NC 256
#define SPLITS 8
#define CPS (NN / SPLITS)   // 1024 columns per split
#define TILE 128
#define NCHUNK (DD / 8)     // 16 k-chunks of 8

typedef unsigned long long u64t;

// Scratch (device globals — no allocation allowed)
__device__ float g_xn[NN * DD];
__device__ float g_sq[NN];
__device__ int   g_lab[NN];
__device__ int   g_cnt[NC];
__device__ int   g_is64;
__device__ float g_posV[SPLITS * NN];
__device__ int   g_posI[SPLITS * NN];
__device__ float g_negV[SPLITS * NN];
__device__ int   g_negI[SPLITS * NN];

#define F_INF  __int_as_float(0x7f800000)

// Packed fp32x2 helpers (each lane is IEEE fp32 fma.rn — bitwise identical
// to scalar fmaf; FFMA2 reachable only via PTX)
__device__ __forceinline__ u64t pack2_dup(float v) {
    u64t r; asm("mov.b64 %0, {%1, %1};" : "=l"(r) : "f"(v)); return r;
}
__device__ __forceinline__ void ffma2(u64t& d, u64t a, u64t b) {
    asm("fma.rn.f32x2 %0, %1, %2, %0;" : "+l"(d) : "l"(a), "l"(b));
}
__device__ __forceinline__ void unpack2(float& lo, float& hi, u64t v) {
    asm("mov.b64 {%0, %1}, %2;" : "=f"(lo), "=f"(hi) : "l"(v));
}

// Detect whether labels are stored as int64 (labels < 256 => high words zero)
__global__ void detect_kernel(const int* __restrict__ labw) {
    if (threadIdx.x == 0) {
        int any = 0;
        for (int i = 0; i < 256; i++) any |= labw[2 * i + 1];
        g_is64 = (any == 0) ? 1 : 0;
    }
}

__global__ void convert_labels_kernel(const void* __restrict__ labels) {
    int i = blockIdx.x * blockDim.x + threadIdx.x;
    if (i >= NN) return;
    int v;
    if (g_is64) v = (int)((const long long*)labels)[i];
    else        v = ((const int*)labels)[i];
    g_lab[i] = v;
    if (i < NC) g_cnt[i] = 0;
}

__global__ void hist_kernel() {
    int i = blockIdx.x * blockDim.x + threadIdx.x;
    if (i < NN) atomicAdd(&g_cnt[g_lab[i] & (NC - 1)], 1);
}

// One block (128 threads) per row: normalize, then recompute sq of normalized row
__global__ void normalize_kernel(const float* __restrict__ x) {
    int row = blockIdx.x;
    int t = threadIdx.x;
    float v = x[row * DD + t];
    float s = v * v;
    #pragma unroll
    for (int o = 16; o > 0; o >>= 1) s += __shfl_xor_sync(0xffffffffu, s, o);
    __shared__ float ws[4];
    __shared__ float ws2[4];
    int warp = t >> 5, lane = t & 31;
    if (lane == 0) ws[warp] = s;
    __syncthreads();
    float tot = ws[0] + ws[1] + ws[2] + ws[3];
    float nrm = __fsqrt_rn(tot);          // IEEE, matches jnp
    float xn  = __fdiv_rn(v, nrm);        // IEEE divide, matches x / norm
    g_xn[row * DD + t] = xn;
    float s2 = xn * xn;
    #pragma unroll
    for (int o = 16; o > 0; o >>= 1) s2 += __shfl_xor_sync(0xffffffffu, s2, o);
    if (lane == 0) ws2[warp] = s2;
    __syncthreads();
    if (t == 0) g_sq[row] = ws2[0] + ws2[1] + ws2[2] + ws2[3];
}

// SGEMM-style miner: CTA = 128 anchor rows x one 1024-column split.
// 256 threads; SPLIT 4+4 micro-tile (rows ty*4 & 64+ty*4, cols tx*4 & 64+tx*4)
// -> conflict-free LDS.128 fragment loads. Double-buffered k-chunks (1 sync
// per chunk). FFMA2 packed math. Warp-shuffle final reduction (no smem).
__global__ void __launch_bounds__(256, 2)
mine_kernel() {
    const int rowBase  = blockIdx.x * TILE;
    const int colStart = blockIdx.y * CPS;

    __shared__ float sA[2][8][TILE];
    __shared__ float sB[2][8][TILE];
    __shared__ float sSqRow[TILE];
    __shared__ float sSqCol[TILE];
    __shared__ int   sLabRow[TILE];
    __shared__ int   sLabCol[TILE];

    const int tid = threadIdx.x;
    const int tx = tid & 15;      // column group 0..15
    const int ty = tid >> 4;      // row group 0..15

    if (tid < TILE) {
        sLabRow[tid] = g_lab[rowBase + tid];
        sSqRow[tid]  = g_sq[rowBase + tid];
    }

    float posV[8], negV[8];
    int   posI[8], negI[8];
    #pragma unroll
    for (int ii = 0; ii < 8; ii++) {
        posV[ii] = -1.0f;  posI[ii] = 0x7fffffff;
        negV[ii] = F_INF;  negI[ii] = 0x7fffffff;
    }

    const int loadRow = tid >> 1;          // 0..127
    const int loadK4  = (tid & 1) * 4;     // 0 or 4
    const float* gA = &g_xn[(rowBase + loadRow) * DD + loadK4];

    for (int tile = 0; tile < CPS / TILE; ++tile) {
        const int colBase = colStart + tile * TILE;
        __syncthreads();   // prev epilogue done with sLabCol/sSqCol; prev compute done with sA/sB
        if (tid < TILE) {
            sLabCol[tid] = g_lab[colBase + tid];
            sSqCol[tid]  = g_sq[colBase + tid];
        }
        const float* gB = &g_xn[(colBase + loadRow) * DD + loadK4];

        // preload chunk 0 into buffer 0
        float4 av = *(const float4*)&gA[0];
        float4 bv = *(const float4*)&gB[0];
        sA[0][loadK4 + 0][loadRow] = av.x;
        sA[0][loadK4 + 1][loadRow] = av.y;
        sA[0][loadK4 + 2][loadRow] = av.z;
        sA[0][loadK4 + 3][loadRow] = av.w;
        sB[0][loadK4 + 0][loadRow] = bv.x;
        sB[0][loadK4 + 1][loadRow] = bv.y;
        sB[0][loadK4 + 2][loadRow] = bv.z;
        sB[0][loadK4 + 3][loadRow] = bv.w;
        __syncthreads();

        u64t acc2[8][4];
        #pragma unroll
        for (int i = 0; i < 8; i++)
            #pragma unroll
            for (int p = 0; p < 4; p++) acc2[i][p] = 0ull;

        #pragma unroll 1
        for (int c = 0; c < NCHUNK; ++c) {
            const int buf = c & 1;
            if (c + 1 < NCHUNK) {
                av = *(const float4*)&gA[(c + 1) * 8];
                bv = *(const float4*)&gB[(c + 1) * 8];
            }
            #pragma unroll
            for (int k = 0; k < 8; k++) {
                // conflict-free fragment loads: 16 lanes x 16B contiguous
                float4 a0 = *(const float4*)&sA[buf][k][ty * 4];
                float4 a1 = *(const float4*)&sA[buf][k][64 + ty * 4];
                ulonglong2 bq0 = *(const ulonglong2*)&sB[buf][k][tx * 4];
                ulonglong2 bq1 = *(const ulonglong2*)&sB[buf][k][64 + tx * 4];
                u64t bp[4] = {bq0.x, bq0.y, bq1.x, bq1.y};
                u64t a2[8];
                a2[0] = pack2_dup(a0.x); a2[1] = pack2_dup(a0.y);
                a2[2] = pack2_dup(a0.z); a2[3] = pack2_dup(a0.w);
                a2[4] = pack2_dup(a1.x); a2[5] = pack2_dup(a1.y);
                a2[6] = pack2_dup(a1.z); a2[7] = pack2_dup(a1.w);
                #pragma unroll
                for (int i = 0; i < 8; i++)
                    #pragma unroll
                    for (int p = 0; p < 4; p++)
                        ffma2(acc2[i][p], a2[i], bp[p]);
            }
            if (c + 1 < NCHUNK) {
                const int nb = (c + 1) & 1;
                sA[nb][loadK4 + 0][loadRow] = av.x;
                sA[nb][loadK4 + 1][loadRow] = av.y;
                sA[nb][loadK4 + 2][loadRow] = av.z;
                sA[nb][loadK4 + 3][loadRow] = av.w;
                sB[nb][loadK4 + 0][loadRow] = bv.x;
                sB[nb][loadK4 + 1][loadRow] = bv.y;
                sB[nb][loadK4 + 2][loadRow] = bv.z;
                sB[nb][loadK4 + 3][loadRow] = bv.w;
                __syncthreads();
            }
        }

        // Epilogue: dist = sqrt(max(sq_i + sq_j - 2*dot, 0)); IEEE sqrt to
        // reproduce reference values. Positives->0, negatives->+inf masks;
        // strict compares keep first (smallest) index; scan order increasing jc.
        #pragma unroll
        for (int ii = 0; ii < 8; ii++) {
            const int  ri  = (ii < 4) ? (ty * 4 + ii) : (64 + ty * 4 + ii - 4);
            const int  i   = rowBase + ri;
            const int  lr  = sLabRow[ri];
            const float sr = sSqRow[ri];
            #pragma unroll
            for (int p = 0; p < 4; p++) {
                float d_lo, d_hi;
                unpack2(d_lo, d_hi, acc2[ii][p]);
                const float dotv[2] = {d_lo, d_hi};
                #pragma unroll
                for (int q = 0; q < 2; q++) {
                    const int jc = (p < 2) ? (tx * 4 + p * 2 + q)
                                           : (64 + tx * 4 + (p - 2) * 2 + q);
                    const int j  = colBase + jc;
                    float d2 = fmaxf(sr + sSqCol[jc] - 2.0f * dotv[q], 0.0f);
                    float dist = __fsqrt_rn(d2);
                    const bool same = (lr == sLabCol[jc]);
                    const float pv = (same && (i != j)) ? dist : 0.0f;
                    if (pv > posV[ii]) { posV[ii] = pv; posI[ii] = j; }
                    const float nv = same ? F_INF : dist;
                    if (nv < negV[ii]) { negV[ii] = nv; negI[ii] = j; }
                }
            }
        }
    }

    // Final reduction over the 16 tx threads of each row group: they are one
    // 16-lane half-warp (lane = (ty&1)*16 + tx) -> width-16 shuffle tree.
    #pragma unroll
    for (int ii = 0; ii < 8; ii++) {
        float pv = posV[ii]; int pi = posI[ii];
        float nv = negV[ii]; int ni = negI[ii];
        #pragma unroll
        for (int off = 8; off > 0; off >>= 1) {
            float opv = __shfl_down_sync(0xffffffffu, pv, off, 16);
            int   opi = __shfl_down_sync(0xffffffffu, pi, off, 16);
            float onv = __shfl_down_sync(0xffffffffu, nv, off, 16);
            int   oni = __shfl_down_sync(0xffffffffu, ni, off, 16);
            if (opv > pv || (opv == pv && opi < pi)) { pv = opv; pi = opi; }
            if (onv < nv || (onv == nv && oni < ni)) { nv = onv; ni = oni; }
        }
        if (tx == 0) {
            const int ri = (ii < 4) ? (ty * 4 + ii) : (64 + ty * 4 + ii - 4);
            const int gi = rowBase + ri;
            g_posV[blockIdx.y * NN + gi] = pv;
            g_posI[blockIdx.y * NN + gi] = pi;
            g_negV[blockIdx.y * NN + gi] = nv;
            g_negI[blockIdx.y * NN + gi] = ni;
        }
    }
}

// Outputs written as FLOAT32 (harness normalizes reference int/bool outputs
// to float32; indices < 8192 exactly representable).
__global__ void final_kernel(float* __restrict__ out) {
    int i = blockIdx.x * blockDim.x + threadIdx.x;
    if (i >= NN) return;
    float bpv = -1.0f;  int bpi = 0x7fffffff;
    float bnv = F_INF;  int bni = 0x7fffffff;
    #pragma unroll
    for (int s = 0; s < SPLITS; s++) {
        float v = g_posV[s * NN + i]; int id = g_posI[s * NN + i];
        if (v > bpv || (v == bpv && id < bpi)) { bpv = v; bpi = id; }
        v = g_negV[s * NN + i]; id = g_negI[s * NN + i];
        if (v < bnv || (v == bnv && id < bni)) { bnv = v; bni = id; }
    }
    const int c = g_cnt[g_lab[i] & (NC - 1)];
    const float keep = (c >= 2 && c < NN) ? 1.0f : 0.0f;
    out[0 * NN + i] = (float)i;    // anchor_inds
    out[1 * NN + i] = (float)bpi;  // hardest_pos_inds
    out[2 * NN + i] = (float)bni;  // hardest_neg_inds
    out[3 * NN + i] = keep;        // keep
}

extern "C" void kernel_launch(void* const* d_in, const int* in_sizes, int n_in,
                              void* d_out, int out_size) {
    const float* embeds = (const float*)d_in[0];
    const void*  labels = d_in[1];
    float* out = (float*)d_out;

    detect_kernel<<<1, 32>>>((const int*)labels);
    convert_labels_kernel<<<(NN + 255) / 256, 256>>>(labels);
    hist_kernel<<<(NN + 255) / 256, 256>>>();
    normalize_kernel<<<NN, DD>>>(embeds);
    dim3 grid(NN / TILE, SPLITS);
    mine_kernel<<<grid, 256>>>();
    final_kernel<<<(NN + 255) / 256, 256>>>(out);
}

// round 6
// speedup vs baseline: 2.3746x; 2.0785x over previous
#include <cuda_runtime.h>
#include <math.h>

#define NN 8192
#define DD 128
#define NC 256
#define TILE 128
#define NTILE (NN / TILE)                   // 64
#define NPAIRS (NTILE * (NTILE + 1) / 2)    // 2080
#define NCHUNK (DD / 8)                     // 16 k-chunks of 8

typedef unsigned long long u64t;

// Scratch (device globals — no allocation allowed)
__device__ float g_xn[NN * DD];
__device__ float g_sq[NN];
__device__ int   g_lab[NN];
__device__ int   g_cnt[NC];
__device__ int   g_is64;
__device__ u64t  g_posP[NN];   // packed (bits(dist)<<32)|(NN-1-j), merged via atomicMax
__device__ u64t  g_negP[NN];   // packed (bits(dist)<<32)|j,        merged via atomicMin

#define F_INF  __int_as_float(0x7f800000)

// Packed fp32x2 helpers (each lane is IEEE fp32 fma.rn — bitwise identical to
// scalar fmaf). FFMA2 is throughput-neutral on sm_103a but halves instr count.
__device__ __forceinline__ u64t pack2_dup(float v) {
    u64t r; asm("mov.b64 %0, {%1, %1};" : "=l"(r) : "f"(v)); return r;
}
__device__ __forceinline__ void ffma2(u64t& d, u64t a, u64t b) {
    asm("fma.rn.f32x2 %0, %1, %2, %0;" : "+l"(d) : "l"(a), "l"(b));
}
__device__ __forceinline__ void unpack2(float& lo, float& hi, u64t v) {
    asm("mov.b64 {%0, %1}, %2;" : "=f"(lo), "=f"(hi) : "l"(v));
}

__device__ __forceinline__ u64t packPos(float v, int j) {
    return ((u64t)__float_as_uint(v) << 32) | (u64t)(NN - 1 - j);
}
__device__ __forceinline__ u64t packNeg(float v, int j) {
    return ((u64t)__float_as_uint(v) << 32) | (u64t)j;
}

// Detect whether labels are stored as int64 (labels < 256 => high words zero)
__global__ void detect_kernel(const int* __restrict__ labw) {
    if (threadIdx.x == 0) {
        int any = 0;
        for (int i = 0; i < 256; i++) any |= labw[2 * i + 1];
        g_is64 = (any == 0) ? 1 : 0;
    }
}

__global__ void convert_labels_kernel(const void* __restrict__ labels) {
    int i = blockIdx.x * blockDim.x + threadIdx.x;
    if (i >= NN) return;
    int v;
    if (g_is64) v = (int)((const long long*)labels)[i];
    else        v = ((const int*)labels)[i];
    g_lab[i] = v;
    g_posP[i] = 0ull;            // any entry (dist>=0) wins or ties
    g_negP[i] = ~0ull;           // any entry smaller
    if (i < NC) g_cnt[i] = 0;
}

__global__ void hist_kernel() {
    int i = blockIdx.x * blockDim.x + threadIdx.x;
    if (i < NN) atomicAdd(&g_cnt[g_lab[i] & (NC - 1)], 1);
}

// One block (128 threads) per row: normalize, then recompute sq of normalized row
__global__ void normalize_kernel(const float* __restrict__ x) {
    int row = blockIdx.x;
    int t = threadIdx.x;
    float v = x[row * DD + t];
    float s = v * v;
    #pragma unroll
    for (int o = 16; o > 0; o >>= 1) s += __shfl_xor_sync(0xffffffffu, s, o);
    __shared__ float ws[4];
    __shared__ float ws2[4];
    int warp = t >> 5, lane = t & 31;
    if (lane == 0) ws[warp] = s;
    __syncthreads();
    float tot = ws[0] + ws[1] + ws[2] + ws[3];
    float nrm = __fsqrt_rn(tot);          // IEEE, matches jnp
    float xn  = __fdiv_rn(v, nrm);        // IEEE divide, matches x / norm
    g_xn[row * DD + t] = xn;
    float s2 = xn * xn;
    #pragma unroll
    for (int o = 16; o > 0; o >>= 1) s2 += __shfl_xor_sync(0xffffffffu, s2, o);
    if (lane == 0) ws2[warp] = s2;
    __syncthreads();
    if (t == 0) g_sq[row] = ws2[0] + ws2[1] + ws2[2] + ws2[3];
}

// Triangular miner: one CTA per 128x128 tile (I,J), J >= I. d(i,j)=d(j,i)
// bitwise (same k-order FMA chain), so off-diagonal tiles serve BOTH row
// anchors (rows I x cands J) and col anchors (rows J x cands I). Merging via
// packed u64 atomics encodes the exact argmax/argmin-first-index tie rule.
__global__ void __launch_bounds__(256, 2)
mine_kernel() {
    // decode triangular pair index
    int t = blockIdx.x, I = 0;
    while (t >= NTILE - I) { t -= NTILE - I; I++; }
    const int J = I + t;
    const int rowBase = I * TILE;
    const int colBase = J * TILE;
    const bool offdiag = (I != J);

    __shared__ float sA[2][8][TILE];
    __shared__ float sB[2][8][TILE];
    __shared__ float sSqRow[TILE];
    __shared__ float sSqCol[TILE];
    __shared__ int   sLabRow[TILE];
    __shared__ int   sLabCol[TILE];
    __shared__ u64t  sPc[TILE];
    __shared__ u64t  sNc[TILE];

    const int tid = threadIdx.x;
    const int tx = tid & 15;      // column group 0..15
    const int ty = tid >> 4;      // row group 0..15

    if (tid < TILE) {
        sLabRow[tid] = g_lab[rowBase + tid];
        sSqRow[tid]  = g_sq[rowBase + tid];
        sLabCol[tid] = g_lab[colBase + tid];
        sSqCol[tid]  = g_sq[colBase + tid];
        sPc[tid] = 0ull;
        sNc[tid] = ~0ull;
    }

    const int loadRow = tid >> 1;          // 0..127
    const int loadK4  = (tid & 1) * 4;     // 0 or 4
    const float* gA = &g_xn[(rowBase + loadRow) * DD + loadK4];
    const float* gB = &g_xn[(colBase + loadRow) * DD + loadK4];

    // preload chunk 0 into buffer 0
    float4 av = *(const float4*)&gA[0];
    float4 bv = *(const float4*)&gB[0];
    sA[0][loadK4 + 0][loadRow] = av.x;
    sA[0][loadK4 + 1][loadRow] = av.y;
    sA[0][loadK4 + 2][loadRow] = av.z;
    sA[0][loadK4 + 3][loadRow] = av.w;
    sB[0][loadK4 + 0][loadRow] = bv.x;
    sB[0][loadK4 + 1][loadRow] = bv.y;
    sB[0][loadK4 + 2][loadRow] = bv.z;
    sB[0][loadK4 + 3][loadRow] = bv.w;
    __syncthreads();

    u64t acc2[8][4];
    #pragma unroll
    for (int i = 0; i < 8; i++)
        #pragma unroll
        for (int p = 0; p < 4; p++) acc2[i][p] = 0ull;

    #pragma unroll 1
    for (int c = 0; c < NCHUNK; ++c) {
        const int buf = c & 1;
        if (c + 1 < NCHUNK) {
            av = *(const float4*)&gA[(c + 1) * 8];
            bv = *(const float4*)&gB[(c + 1) * 8];
        }
        #pragma unroll
        for (int k = 0; k < 8; k++) {
            float4 a0 = *(const float4*)&sA[buf][k][ty * 4];
            float4 a1 = *(const float4*)&sA[buf][k][64 + ty * 4];
            ulonglong2 bq0 = *(const ulonglong2*)&sB[buf][k][tx * 4];
            ulonglong2 bq1 = *(const ulonglong2*)&sB[buf][k][64 + tx * 4];
            u64t bp[4] = {bq0.x, bq0.y, bq1.x, bq1.y};
            u64t a2[8];
            a2[0] = pack2_dup(a0.x); a2[1] = pack2_dup(a0.y);
            a2[2] = pack2_dup(a0.z); a2[3] = pack2_dup(a0.w);
            a2[4] = pack2_dup(a1.x); a2[5] = pack2_dup(a1.y);
            a2[6] = pack2_dup(a1.z); a2[7] = pack2_dup(a1.w);
            #pragma unroll
            for (int i = 0; i < 8; i++)
                #pragma unroll
                for (int p = 0; p < 4; p++)
                    ffma2(acc2[i][p], a2[i], bp[p]);
        }
        if (c + 1 < NCHUNK) {
            const int nb = (c + 1) & 1;
            sA[nb][loadK4 + 0][loadRow] = av.x;
            sA[nb][loadK4 + 1][loadRow] = av.y;
            sA[nb][loadK4 + 2][loadRow] = av.z;
            sA[nb][loadK4 + 3][loadRow] = av.w;
            sB[nb][loadK4 + 0][loadRow] = bv.x;
            sB[nb][loadK4 + 1][loadRow] = bv.y;
            sB[nb][loadK4 + 2][loadRow] = bv.z;
            sB[nb][loadK4 + 3][loadRow] = bv.w;
            __syncthreads();
        }
    }

    // Col-anchor packed stats (candidate index = row i; invi for pos ties)
    u64t colP[8], colN[8];
    #pragma unroll
    for (int s = 0; s < 8; s++) { colP[s] = 0ull; colN[s] = ~0ull; }

    // Epilogue: dist = sqrt(max(sq_i + sq_j - 2*dot, 0)); IEEE sqrt to
    // reproduce reference values exactly. Row-side: candidates = tile cols;
    // col-side (offdiag only): candidates = tile rows, same dist values.
    #pragma unroll
    for (int ii = 0; ii < 8; ii++) {
        const int  ri  = (ii < 4) ? (ty * 4 + ii) : (64 + ty * 4 + ii - 4);
        const int  i   = rowBase + ri;
        const int  lr  = sLabRow[ri];
        const float sr = sSqRow[ri];
        u64t rp = 0ull, rn = ~0ull;
        #pragma unroll
        for (int p = 0; p < 4; p++) {
            float d_lo, d_hi;
            unpack2(d_lo, d_hi, acc2[ii][p]);
            const float dotv[2] = {d_lo, d_hi};
            #pragma unroll
            for (int q = 0; q < 2; q++) {
                const int s  = p * 2 + q;
                const int jc = (p < 2) ? (tx * 4 + p * 2 + q)
                                       : (64 + tx * 4 + (p - 2) * 2 + q);
                const int j  = colBase + jc;
                float d2 = fmaxf(sr + sSqCol[jc] - 2.0f * dotv[q], 0.0f);
                float dist = __fsqrt_rn(d2);
                const bool same = (lr == sLabCol[jc]);
                const bool diag = (i == j);
                // row anchor i, candidate j
                const float pv = (same && !diag) ? dist : 0.0f;
                const float nv = same ? F_INF : dist;
                u64t pp = packPos(pv, j);
                if (pp > rp) rp = pp;
                u64t np = packNeg(nv, j);
                if (np < rn) rn = np;
                // col anchor j, candidate i (offdiag: i != j always)
                u64t cp = packPos(pv, i);   // same mask values by symmetry
                if (cp > colP[s]) colP[s] = cp;
                u64t cn = packNeg(nv, i);
                if (cn < colN[s]) colN[s] = cn;
            }
        }
        // reduce row stats over the 16 tx threads (one 16-lane half-warp)
        #pragma unroll
        for (int off = 8; off > 0; off >>= 1) {
            u64t orp = __shfl_down_sync(0xffffffffu, rp, off, 16);
            u64t orn = __shfl_down_sync(0xffffffffu, rn, off, 16);
            if (orp > rp) rp = orp;
            if (orn < rn) rn = orn;
        }
        if (tx == 0) {
            atomicMax(&g_posP[i], rp);
            atomicMin(&g_negP[i], rn);
        }
    }

    if (offdiag) {
        // merge col stats into smem, then one global RED per column
        #pragma unroll
        for (int p = 0; p < 4; p++) {
            #pragma unroll
            for (int q = 0; q < 2; q++) {
                const int s  = p * 2 + q;
                const int jc = (p < 2) ? (tx * 4 + p * 2 + q)
                                       : (64 + tx * 4 + (p - 2) * 2 + q);
                atomicMax(&sPc[jc], colP[s]);
                atomicMin(&sNc[jc], colN[s]);
            }
        }
        __syncthreads();
        if (tid < TILE) {
            atomicMax(&g_posP[colBase + tid], sPc[tid]);
            atomicMin(&g_negP[colBase + tid], sNc[tid]);
        }
    }
}

// Outputs written as FLOAT32 (harness normalizes reference int/bool outputs
// to float32; indices < 8192 exactly representable).
__global__ void final_kernel(float* __restrict__ out) {
    int i = blockIdx.x * blockDim.x + threadIdx.x;
    if (i >= NN) return;
    const int bpi = NN - 1 - (int)(g_posP[i] & 0xffffffffu);
    const int bni = (int)(g_negP[i] & 0xffffffffu);
    const int c = g_cnt[g_lab[i] & (NC - 1)];
    const float keep = (c >= 2 && c < NN) ? 1.0f : 0.0f;
    out[0 * NN + i] = (float)i;    // anchor_inds
    out[1 * NN + i] = (float)bpi;  // hardest_pos_inds
    out[2 * NN + i] = (float)bni;  // hardest_neg_inds
    out[3 * NN + i] = keep;        // keep
}

extern "C" void kernel_launch(void* const* d_in, const int* in_sizes, int n_in,
                              void* d_out, int out_size) {
    const float* embeds = (const float*)d_in[0];
    const void*  labels = d_in[1];
    float* out = (float*)d_out;

    detect_kernel<<<1, 32>>>((const int*)labels);
    convert_labels_kernel<<<(NN + 255) / 256, 256>>>(labels);
    hist_kernel<<<(NN + 255) / 256, 256>>>();
    normalize_kernel<<<NN, DD>>>(embeds);
    mine_kernel<<<NPAIRS, 256>>>();
    final_kernel<<<(NN + 255) / 256, 256>>>(out);
}